// round 5
// baseline (speedup 1.0000x reference)
#include <cuda_runtime.h>
#include <stdint.h>

// ---------------------------------------------------------------------------
// _multiCodebookQuantization: N=16, M=4, D=32, K=256, H=W=64
// outputs (concatenated, f32): sample (n,m,h,w,k) | code (n,m,h,w) | logit (n,m,h,w,k)
// ---------------------------------------------------------------------------

// RNG reproduction of jax.random.categorical(jax.random.key(42), logit):
//   mode 0: jax_threefry_partitionable=True (default since jax 0.4.30):
//           per-element i: threefry2x32(key,(hi32(i),lo32(i))), bits = o0 ^ o1
//   mode 1/2: partitionable but single-lane (o0 / o1)  [fallback guesses]
//   mode 3: legacy: iota split in halves -> bits[i<T/2]=o0(block i), bits[i>=T/2]=o1
#define RNG_MODE 0

static constexpr int   TPB          = 128;
static constexpr long  SAMPLE_ELEMS = 67108864L;   // 16*4*64*64*256
static constexpr long  CODE_ELEMS   = 262144L;     // 16*4*64*64
static constexpr unsigned HALF_T    = 33554432u;   // total gumbel elems / 2 (mode 3)

// --- accurate logf (~0.85 ulp, FMA-only polynomial; input positive, normal) ---
__device__ __forceinline__ float alogf(float a) {
    int   e = (__float_as_int(a) - 0x3f2aaaab) & 0xff800000;
    float m = __int_as_float(__float_as_int(a) - e);
    float i = (float)e * 1.19209290e-7f;        // e * 2^-23
    m = m - 1.0f;                                // m in [-1/3, 1/3]
    float s = m * m;
    float r = -0.130310059f;
    float t =  0.140869141f;
    r = fmaf(r, s, -0.121483512f);
    t = fmaf(t, s,  0.139814854f);
    r = fmaf(r, s, -0.166846126f);
    t = fmaf(t, s,  0.200120345f);
    r = fmaf(r, s, -0.249996200f);
    r = fmaf(t, m, r);
    r = fmaf(r, m,  0.333331972f);
    r = fmaf(r, m, -0.500000000f);
    r = fmaf(r, s, m);
    r = fmaf(i, 0.693147182f, r);
    return r;
}

// --- Threefry-2x32, 20 rounds, key = (0, 42) (jax.random.key(42)) ---
__device__ __forceinline__ void threefry42(uint32_t x0, uint32_t x1,
                                           uint32_t& o0, uint32_t& o1) {
    const uint32_t ks1 = 42u;
    const uint32_t ks2 = 0x1BD11BDAu ^ 42u;   // ks0 = 0
    x1 += ks1;                                 // x0 += ks0 (= 0)
#define TFR(r) { x0 += x1; x1 = __funnelshift_l(x1, x1, (r)); x1 ^= x0; }
    TFR(13) TFR(15) TFR(26) TFR(6)
    x0 += ks1; x1 += ks2 + 1u;
    TFR(17) TFR(29) TFR(16) TFR(24)
    x0 += ks2; x1 += 2u;                       // + ks0
    TFR(13) TFR(15) TFR(26) TFR(6)
    /* x0 += ks0 */ x1 += ks1 + 3u;
    TFR(17) TFR(29) TFR(16) TFR(24)
    x0 += ks1; x1 += ks2 + 4u;
    TFR(13) TFR(15) TFR(26) TFR(6)
    x0 += ks2; x1 += 5u;                       // + ks0
#undef TFR
    o0 = x0; o1 = x1;
}

// bits for flat gumbel index i (see RNG_MODE)
__device__ __forceinline__ uint32_t gumbel_bits(uint32_t i) {
    uint32_t r0, r1;
#if RNG_MODE == 0
    threefry42(0u, i, r0, r1);
    return r0 ^ r1;
#elif RNG_MODE == 1
    threefry42(0u, i, r0, r1);
    return r0;
#elif RNG_MODE == 2
    threefry42(0u, i, r0, r1);
    return r1;
#else
    if (i < HALF_T) { threefry42(i, i + HALF_T, r0, r1); return r0; }
    else            { threefry42(i - HALF_T, i, r0, r1); return r1; }
#endif
}

// JAX gumbel: u = max(tiny, uniform_bits + tiny); g = -log(-log(u))
__device__ __forceinline__ float gumbel_from_bits(uint32_t bits) {
    float f = __uint_as_float((bits >> 9) | 0x3F800000u) - 1.0f;  // [0,1)
    float u = fmaxf(1.17549435e-38f, f + 1.17549435e-38f);
    float e = -alogf(u);          // -log(u) in (1.19e-7, 87.34]
    return -alogf(e);
}

// ---------------------------------------------------------------------------
__global__ void mcq_zerofill(float4* __restrict__ p) {
    size_t i = (size_t)blockIdx.x * blockDim.x + threadIdx.x;
    p[i] = make_float4(0.f, 0.f, 0.f, 0.f);
}

__global__ __launch_bounds__(TPB)
void mcq_main(const float* __restrict__ x,
              const float* __restrict__ cbg,
              float* __restrict__ out_sample,
              float* __restrict__ out_code,
              float* __restrict__ out_logit) {
    __shared__ float cb_s[256 * 32];   // codebook[m], row-major [k][d]
    __shared__ float c2_s[256];

    const int tid  = threadIdx.x;
    const int b    = blockIdx.x;        // 0..2047
    const int tile = b & 31;            // 32 tiles of 128 hw positions
    const int m    = (b >> 5) & 3;
    const int n    = b >> 7;            // 0..15

    // load codebook slice for m (8192 floats) into smem
    const float4* cbm4 = reinterpret_cast<const float4*>(cbg + (size_t)m * 256 * 32);
    float4* cb_s4 = reinterpret_cast<float4*>(cb_s);
    #pragma unroll
    for (int i = tid; i < 2048; i += TPB) cb_s4[i] = cbm4[i];
    __syncthreads();

    // c2[k] = sum_d cb[k][d]^2  (plain mul+add, mimicking XLA's mul-then-reduce)
    for (int k = tid; k < 256; k += TPB) {
        float s = 0.f;
        #pragma unroll
        for (int d = 0; d < 32; d++)
            s = __fadd_rn(s, __fmul_rn(cb_s[k * 32 + d], cb_s[k * 32 + d]));
        c2_s[k] = s;
    }
    __syncthreads();

    const int hw  = tile * TPB + tid;               // 0..4095
    const int pos = (n * 4 + m) * 4096 + hw;        // flat (n,m,h,w)

    // load x vector (32 channels, stride H*W) + x2
    const float* xp = x + ((size_t)(n * 128 + m * 32)) * 4096 + hw;
    float xa[32];
    float x2 = 0.f;
    #pragma unroll
    for (int d = 0; d < 32; d++) {
        xa[d] = xp[(size_t)d * 4096];
        x2 = __fadd_rn(x2, __fmul_rn(xa[d], xa[d]));
    }

    const float4* cb4 = reinterpret_cast<const float4*>(cb_s);
    float4* lrow4 = reinterpret_cast<float4*>(out_logit + (size_t)pos * 256);
    const uint32_t ctr0 = (uint32_t)pos * 256u;

    float best = -1e38f, bdist = 1.f, sum = 0.f;
    int   bidx = 0;

    #pragma unroll 1
    for (int k4 = 0; k4 < 64; k4++) {
        float4 lv;
        #pragma unroll
        for (int j = 0; j < 4; j++) {
            const int k = k4 * 4 + j;
            // dot(x, codebook[k]) with 4 partial sums
            float d0 = 0.f, d1 = 0.f, d2 = 0.f, d3 = 0.f;
            #pragma unroll
            for (int q = 0; q < 8; q++) {
                float4 c = cb4[k * 8 + q];
                d0 = fmaf(xa[4 * q + 0], c.x, d0);
                d1 = fmaf(xa[4 * q + 1], c.y, d1);
                d2 = fmaf(xa[4 * q + 2], c.z, d2);
                d3 = fmaf(xa[4 * q + 3], c.w, d3);
            }
            const float dot  = (d0 + d1) + (d2 + d3);
            // dist = (x2 + c2) - 2*dot   (2*dot exact -> fma == mul+sub, 1 rounding)
            const float dist = fmaf(-2.0f, dot, __fadd_rn(x2, c2_s[k]));
            sum += dist;

            const float l = alogf(dist);               // logit output + decision
            (&lv.x)[j] = l;

            const float g = gumbel_from_bits(gumbel_bits(ctr0 + (uint32_t)k));
            const float v = l + g;
            if (v > best) { best = v; bidx = k; bdist = dist; }
        }
        lrow4[k4] = lv;   // coalesced-row float4 store of logits
    }

    // probs[idx] = softmax(log dist)[idx] == dist_idx / sum(dist)
    const float p = bdist / sum;
    out_sample[(size_t)pos * 256 + bidx] = (1.0f + p) - p;  // hard + probs - sg(probs)
    out_code[pos] = (float)bidx;
}

// ---------------------------------------------------------------------------
extern "C" void kernel_launch(void* const* d_in, const int* in_sizes, int n_in,
                              void* d_out, int out_size) {
    const float* x  = (const float*)d_in[0];   // (16, 128, 64, 64) f32
    const float* cb = (const float*)d_in[1];   // (4, 256, 32)      f32

    float* out        = (float*)d_out;
    float* out_sample = out;                                  // 67,108,864
    float* out_code   = out + SAMPLE_ELEMS;                   //    262,144
    float* out_logit  = out + SAMPLE_ELEMS + CODE_ELEMS;      // 67,108,864

    // zero the one-hot sample region at full bandwidth (16,777,216 float4)
    mcq_zerofill<<<65536, 256>>>((float4*)out_sample);
    // main fused kernel: distances, logits, threefry gumbel-max, one-hot, code
    mcq_main<<<2048, TPB>>>(x, cb, out_sample, out_code, out_logit);
}